// round 2
// baseline (speedup 1.0000x reference)
#include <cuda_runtime.h>
#include <math.h>

#define BB 4
#define SS 2048
#define DD 1024
#define HH 16
#define HD 64

// Scratch (device globals: the sanctioned no-alloc workaround)
__device__ float g_Q[BB * SS * DD];
__device__ float g_K[BB * SS * DD];
__device__ float g_V[BB * SS * DD];
__device__ float g_C[BB * SS * DD];

// ---------------------------------------------------------------------------
// SGEMM: C[M,N] = A[M,K] * W[N,K]^T + bias[N]
// Block tile 128x128, K-tile 8, 256 threads, 8x8 micro-tile per thread.
// A and W are both row-major with K contiguous (NT gemm).
// ---------------------------------------------------------------------------
__global__ __launch_bounds__(256) void gemm_nt_bias(
    const float* __restrict__ A, const float* __restrict__ W,
    const float* __restrict__ bias, float* __restrict__ C,
    int M, int N, int K)
{
    __shared__ float As[8][128];
    __shared__ float Bs[8][128];

    const int tid = threadIdx.x;
    const int bm = blockIdx.y * 128;
    const int bn = blockIdx.x * 128;
    const int ty = tid >> 4;   // 0..15 -> row group of 8
    const int tx = tid & 15;   // 0..15 -> col group of 8

    const int lrow = tid >> 1;         // 0..127
    const int lc   = (tid & 1) * 4;    // 0 or 4

    const float* Ap = A + (size_t)(bm + lrow) * K + lc;
    const float* Wp = W + (size_t)(bn + lrow) * K + lc;

    float acc[8][8];
#pragma unroll
    for (int i = 0; i < 8; i++)
#pragma unroll
        for (int j = 0; j < 8; j++) acc[i][j] = 0.0f;

    for (int k0 = 0; k0 < K; k0 += 8) {
        float4 av = *(const float4*)(Ap + k0);
        float4 wv = *(const float4*)(Wp + k0);
        As[lc + 0][lrow] = av.x;
        As[lc + 1][lrow] = av.y;
        As[lc + 2][lrow] = av.z;
        As[lc + 3][lrow] = av.w;
        Bs[lc + 0][lrow] = wv.x;
        Bs[lc + 1][lrow] = wv.y;
        Bs[lc + 2][lrow] = wv.z;
        Bs[lc + 3][lrow] = wv.w;
        __syncthreads();

#pragma unroll
        for (int k = 0; k < 8; k++) {
            float4 a0 = *(const float4*)&As[k][ty * 8];
            float4 a1 = *(const float4*)&As[k][ty * 8 + 4];
            float4 b0 = *(const float4*)&Bs[k][tx * 8];
            float4 b1 = *(const float4*)&Bs[k][tx * 8 + 4];
            float a[8] = {a0.x, a0.y, a0.z, a0.w, a1.x, a1.y, a1.z, a1.w};
            float b[8] = {b0.x, b0.y, b0.z, b0.w, b1.x, b1.y, b1.z, b1.w};
#pragma unroll
            for (int i = 0; i < 8; i++)
#pragma unroll
                for (int j = 0; j < 8; j++)
                    acc[i][j] = fmaf(a[i], b[j], acc[i][j]);
        }
        __syncthreads();
    }

    // epilogue: add bias, store
    float bz[8];
#pragma unroll
    for (int j = 0; j < 8; j++) bz[j] = bias[bn + tx * 8 + j];

#pragma unroll
    for (int i = 0; i < 8; i++) {
        float* Crow = C + (size_t)(bm + ty * 8 + i) * N + bn + tx * 8;
        float4 o0, o1;
        o0.x = acc[i][0] + bz[0];
        o0.y = acc[i][1] + bz[1];
        o0.z = acc[i][2] + bz[2];
        o0.w = acc[i][3] + bz[3];
        o1.x = acc[i][4] + bz[4];
        o1.y = acc[i][5] + bz[5];
        o1.z = acc[i][6] + bz[6];
        o1.w = acc[i][7] + bz[7];
        *(float4*)(Crow)     = o0;
        *(float4*)(Crow + 4) = o1;
    }
}

// ---------------------------------------------------------------------------
// Flash-style attention.
// Grid: (S/64 query tiles, B*H). Block: 256 threads.
// Q tile 64x64 (pre-scaled by 1/sqrt(Hd)), KV tiles of 32 rows.
// Online softmax: thread t<64 owns row t (m, l in registers).
// O accumulator: per-thread 4 rows x 4 cols in registers.
// ---------------------------------------------------------------------------
__global__ __launch_bounds__(256) void attn_kernel(
    const float* __restrict__ Q, const float* __restrict__ K,
    const float* __restrict__ V, float* __restrict__ O)
{
    __shared__ float Qs[64][65];
    __shared__ float Ks[32][65];
    __shared__ float Vs[32][65];
    __shared__ float Ps[64][33];
    __shared__ float alpha_s[64];
    __shared__ float l_s[64];

    const int qt = blockIdx.x;
    const int bh = blockIdx.y;
    const int b  = bh >> 4;
    const int h  = bh & 15;

    const int tid = threadIdx.x;
    const int ty = tid >> 4;   // 0..15 -> 4 score/O rows
    const int tx = tid & 15;   // 0..15

    // Load Q tile (scale by 1/8 = 1/sqrt(64))
    const float* Qbase = Q + ((size_t)(b * SS + qt * 64) * DD) + h * HD;
    for (int i = tid; i < 64 * 16; i += 256) {
        int r = i >> 4;
        int c = (i & 15) * 4;
        float4 v = *(const float4*)(Qbase + (size_t)r * DD + c);
        Qs[r][c + 0] = v.x * 0.125f;
        Qs[r][c + 1] = v.y * 0.125f;
        Qs[r][c + 2] = v.z * 0.125f;
        Qs[r][c + 3] = v.w * 0.125f;
    }

    float m_r = -INFINITY;   // valid for tid < 64
    float l_r = 0.0f;

    float acc[4][4];
#pragma unroll
    for (int i = 0; i < 4; i++)
#pragma unroll
        for (int j = 0; j < 4; j++) acc[i][j] = 0.0f;

    for (int kt = 0; kt < SS / 32; kt++) {
        __syncthreads();  // previous iteration's reads of Ks/Vs/Ps done

        const float* Kb2 = K + ((size_t)(b * SS + kt * 32) * DD) + h * HD;
        const float* Vb2 = V + ((size_t)(b * SS + kt * 32) * DD) + h * HD;
        for (int i = tid; i < 32 * 16; i += 256) {
            int r = i >> 4;
            int c = (i & 15) * 4;
            float4 kv = *(const float4*)(Kb2 + (size_t)r * DD + c);
            float4 vv = *(const float4*)(Vb2 + (size_t)r * DD + c);
            Ks[r][c + 0] = kv.x; Ks[r][c + 1] = kv.y;
            Ks[r][c + 2] = kv.z; Ks[r][c + 3] = kv.w;
            Vs[r][c + 0] = vv.x; Vs[r][c + 1] = vv.y;
            Vs[r][c + 2] = vv.z; Vs[r][c + 3] = vv.w;
        }
        __syncthreads();

        // S = Qs * Ks^T : rows ty*4..+3, cols tx*2..+1
        float s[4][2];
#pragma unroll
        for (int i = 0; i < 4; i++) { s[i][0] = 0.0f; s[i][1] = 0.0f; }
#pragma unroll 16
        for (int d = 0; d < 64; d++) {
            float k0 = Ks[tx * 2 + 0][d];
            float k1 = Ks[tx * 2 + 1][d];
#pragma unroll
            for (int i = 0; i < 4; i++) {
                float a = Qs[ty * 4 + i][d];
                s[i][0] = fmaf(a, k0, s[i][0]);
                s[i][1] = fmaf(a, k1, s[i][1]);
            }
        }
#pragma unroll
        for (int i = 0; i < 4; i++) {
            Ps[ty * 4 + i][tx * 2 + 0] = s[i][0];
            Ps[ty * 4 + i][tx * 2 + 1] = s[i][1];
        }
        __syncthreads();

        // Online softmax: one thread per row for rows 0..63
        if (tid < 64) {
            float mx = m_r;
#pragma unroll
            for (int j = 0; j < 32; j++) mx = fmaxf(mx, Ps[tid][j]);
            float alpha = __expf(m_r - mx);
            float sum = 0.0f;
#pragma unroll
            for (int j = 0; j < 32; j++) {
                float p = __expf(Ps[tid][j] - mx);
                Ps[tid][j] = p;
                sum += p;
            }
            l_r = l_r * alpha + sum;
            m_r = mx;
            alpha_s[tid] = alpha;
        }
        __syncthreads();

        // Rescale O and accumulate P * V  (O cols tx*4..+3)
        float al[4];
#pragma unroll
        for (int i = 0; i < 4; i++) al[i] = alpha_s[ty * 4 + i];
#pragma unroll
        for (int i = 0; i < 4; i++)
#pragma unroll
            for (int j = 0; j < 4; j++) acc[i][j] *= al[i];

#pragma unroll 8
        for (int j = 0; j < 32; j++) {
            float v0 = Vs[j][tx * 4 + 0];
            float v1 = Vs[j][tx * 4 + 1];
            float v2 = Vs[j][tx * 4 + 2];
            float v3 = Vs[j][tx * 4 + 3];
#pragma unroll
            for (int i = 0; i < 4; i++) {
                float p = Ps[ty * 4 + i][j];
                acc[i][0] = fmaf(p, v0, acc[i][0]);
                acc[i][1] = fmaf(p, v1, acc[i][1]);
                acc[i][2] = fmaf(p, v2, acc[i][2]);
                acc[i][3] = fmaf(p, v3, acc[i][3]);
            }
        }
    }

    if (tid < 64) l_s[tid] = l_r;
    __syncthreads();

    float inv[4];
#pragma unroll
    for (int i = 0; i < 4; i++) inv[i] = 1.0f / l_s[ty * 4 + i];

    float* Ob = O + ((size_t)(b * SS + qt * 64) * DD) + h * HD;
#pragma unroll
    for (int i = 0; i < 4; i++) {
        float4 o;
        o.x = acc[i][0] * inv[i];
        o.y = acc[i][1] * inv[i];
        o.z = acc[i][2] * inv[i];
        o.w = acc[i][3] * inv[i];
        *(float4*)(Ob + (size_t)(ty * 4 + i) * DD + tx * 4) = o;
    }
}

// ---------------------------------------------------------------------------
extern "C" void kernel_launch(void* const* d_in, const int* in_sizes, int n_in,
                              void* d_out, int out_size)
{
    const float* x  = (const float*)d_in[0];
    const float* Wq = (const float*)d_in[1];
    const float* bq = (const float*)d_in[2];
    const float* Wk = (const float*)d_in[3];
    const float* bk = (const float*)d_in[4];
    const float* Wv = (const float*)d_in[5];
    const float* bv = (const float*)d_in[6];
    const float* Wo = (const float*)d_in[7];
    const float* bo = (const float*)d_in[8];
    float* out = (float*)d_out;

    float *qp, *kp, *vp, *cp;
    cudaGetSymbolAddress((void**)&qp, g_Q);
    cudaGetSymbolAddress((void**)&kp, g_K);
    cudaGetSymbolAddress((void**)&vp, g_V);
    cudaGetSymbolAddress((void**)&cp, g_C);

    const int M = BB * SS;  // 8192
    dim3 gemm_grid(DD / 128, M / 128);  // (8, 64)

    gemm_nt_bias<<<gemm_grid, 256>>>(x, Wq, bq, qp, M, DD, DD);
    gemm_nt_bias<<<gemm_grid, 256>>>(x, Wk, bk, kp, M, DD, DD);
    gemm_nt_bias<<<gemm_grid, 256>>>(x, Wv, bv, vp, M, DD, DD);

    dim3 attn_grid(SS / 64, BB * HH);   // (32, 64)
    attn_kernel<<<attn_grid, 256>>>(qp, kp, vp, cp);

    gemm_nt_bias<<<gemm_grid, 256>>>(cp, Wo, bo, out, M, DD, DD);
}

// round 9
// speedup vs baseline: 1.4151x; 1.4151x over previous
#include <cuda_runtime.h>
#include <cuda_bf16.h>
#include <math.h>
#include <stdint.h>

#define BB 4
#define SS 2048
#define DD 1024
#define HH 16
#define HD 64

// Scratch (device globals: the sanctioned no-alloc workaround)
__device__ float g_Q[BB * SS * DD];
__device__ float g_K[BB * SS * DD];
__device__ float g_V[BB * SS * DD];
__device__ float g_C[BB * SS * DD];

// ===========================================================================
// Helpers: ldmatrix + mma.sync (base-PTX, legal on target sm_103)
// ===========================================================================
__device__ __forceinline__ uint32_t smem_u32(const void* p) {
    uint32_t a;
    asm("{ .reg .u64 t; cvta.to.shared.u64 t, %1; cvt.u32.u64 %0, t; }"
        : "=r"(a) : "l"(p));
    return a;
}

#define LDSM4(r, addr) \
    asm volatile("ldmatrix.sync.aligned.m8n8.x4.shared.b16 {%0,%1,%2,%3}, [%4];" \
                 : "=r"((r)[0]), "=r"((r)[1]), "=r"((r)[2]), "=r"((r)[3]) \
                 : "r"(addr))

__device__ __forceinline__ void mma_bf16(float* c, const uint32_t* a,
                                         uint32_t b0, uint32_t b1) {
    asm volatile(
        "mma.sync.aligned.m16n8k16.row.col.f32.bf16.bf16.f32 "
        "{%0,%1,%2,%3}, {%4,%5,%6,%7}, {%8,%9}, {%0,%1,%2,%3};"
        : "+f"(c[0]), "+f"(c[1]), "+f"(c[2]), "+f"(c[3])
        : "r"(a[0]), "r"(a[1]), "r"(a[2]), "r"(a[3]), "r"(b0), "r"(b1));
}

// fp32x4 -> packed bf16x4 hi and residual lo
__device__ __forceinline__ void split4(float4 v, unsigned long long& hi,
                                       unsigned long long& lo) {
    union { __nv_bfloat16 b[4]; unsigned long long u; } ph, pl;
    ph.b[0] = __float2bfloat16_rn(v.x);
    ph.b[1] = __float2bfloat16_rn(v.y);
    ph.b[2] = __float2bfloat16_rn(v.z);
    ph.b[3] = __float2bfloat16_rn(v.w);
    pl.b[0] = __float2bfloat16_rn(v.x - __bfloat162float(ph.b[0]));
    pl.b[1] = __float2bfloat16_rn(v.y - __bfloat162float(ph.b[1]));
    pl.b[2] = __float2bfloat16_rn(v.z - __bfloat162float(ph.b[2]));
    pl.b[3] = __float2bfloat16_rn(v.w - __bfloat162float(ph.b[3]));
    hi = ph.u;
    lo = pl.u;
}

// ===========================================================================
// HMMA GEMM (bf16x3 split): C[M,N] = A[M,K] * W[N,K]^T + bias
// CTA tile 128x64, K-chunk 32, 256 threads (8 warps, warp tile 32x32).
// Smem rows padded to 40 bf16 (80B): 16B-aligned + conflict-free for ldmatrix.
// ===========================================================================
#define GM_BM 128
#define GM_BN 64
#define GM_BK 32
#define GM_PITCH 40

__global__ __launch_bounds__(256) void gemm_mma(
    const float* __restrict__ A, const float* __restrict__ W,
    const float* __restrict__ bias, float* __restrict__ C,
    int M, int N, int K)
{
    __shared__ __nv_bfloat16 Ah[GM_BM][GM_PITCH];
    __shared__ __nv_bfloat16 Al[GM_BM][GM_PITCH];
    __shared__ __nv_bfloat16 Bh[GM_BN][GM_PITCH];
    __shared__ __nv_bfloat16 Bl[GM_BN][GM_PITCH];

    const int tid  = threadIdx.x;
    const int wid  = tid >> 5;
    const int lane = tid & 31;
    const int wm   = wid >> 1;   // 0..3 -> M offset wm*32
    const int wn   = wid & 1;    // 0..1 -> N offset wn*32

    const int bm = blockIdx.y * GM_BM;
    const int bn = blockIdx.x * GM_BN;

    // staging map: 8 threads per row, 4 fp32 each (cols 0..31)
    const int ar = tid >> 3;          // 0..31
    const int ac = (tid & 7) * 4;     // 0,4,...,28

    // ldmatrix lane addressing (precompute element offsets)
    const int la_row = (lane & 7) + ((lane >> 3) & 1) * 8;   // A tile row within 16
    const int la_kc  = (lane >> 4) * 8;                      // A k-offset within 16
    const int lb_row = ((lane >> 4) & 1) * 8 + (lane & 7);   // B n-row within 16
    const int lb_kc  = ((lane >> 3) & 1) * 8;                // B k-offset within 16

    float acc[2][4][4];
#pragma unroll
    for (int mf = 0; mf < 2; mf++)
#pragma unroll
        for (int nf = 0; nf < 4; nf++)
#pragma unroll
            for (int i = 0; i < 4; i++) acc[mf][nf][i] = 0.0f;

    float4 a_st[4];
    float4 b_st[2];

    // preload chunk 0
#pragma unroll
    for (int it = 0; it < 4; it++)
        a_st[it] = *(const float4*)(A + (size_t)(bm + ar + it * 32) * K + ac);
#pragma unroll
    for (int it = 0; it < 2; it++)
        b_st[it] = *(const float4*)(W + (size_t)(bn + ar + it * 32) * K + ac);

    const int nchunks = K / GM_BK;
    for (int ch = 0; ch < nchunks; ch++) {
        // convert + store current chunk
#pragma unroll
        for (int it = 0; it < 4; it++) {
            unsigned long long hi, lo;
            split4(a_st[it], hi, lo);
            *(unsigned long long*)&Ah[ar + it * 32][ac] = hi;
            *(unsigned long long*)&Al[ar + it * 32][ac] = lo;
        }
#pragma unroll
        for (int it = 0; it < 2; it++) {
            unsigned long long hi, lo;
            split4(b_st[it], hi, lo);
            *(unsigned long long*)&Bh[ar + it * 32][ac] = hi;
            *(unsigned long long*)&Bl[ar + it * 32][ac] = lo;
        }
        __syncthreads();

        // issue loads for next chunk (latency hidden behind MMAs)
        if (ch + 1 < nchunks) {
            const int k0 = (ch + 1) * GM_BK;
#pragma unroll
            for (int it = 0; it < 4; it++)
                a_st[it] = *(const float4*)(A + (size_t)(bm + ar + it * 32) * K + k0 + ac);
#pragma unroll
            for (int it = 0; it < 2; it++)
                b_st[it] = *(const float4*)(W + (size_t)(bn + ar + it * 32) * K + k0 + ac);
        }

        // MMAs: 2 k16 steps per chunk
#pragma unroll
        for (int ks = 0; ks < 2; ks++) {
            uint32_t ah[2][4], al[2][4];
            uint32_t bh[2][4], bl[2][4];
#pragma unroll
            for (int mf = 0; mf < 2; mf++) {
                const int r = wm * 32 + mf * 16 + la_row;
                const int c = ks * 16 + la_kc;
                LDSM4(ah[mf], smem_u32(&Ah[r][c]));
                LDSM4(al[mf], smem_u32(&Al[r][c]));
            }
#pragma unroll
            for (int ng = 0; ng < 2; ng++) {
                const int r = wn * 32 + ng * 16 + lb_row;
                const int c = ks * 16 + lb_kc;
                LDSM4(bh[ng], smem_u32(&Bh[r][c]));
                LDSM4(bl[ng], smem_u32(&Bl[r][c]));
            }
#pragma unroll
            for (int mf = 0; mf < 2; mf++) {
#pragma unroll
                for (int nf = 0; nf < 4; nf++) {
                    const int ng = nf >> 1;
                    const int hb = (nf & 1) * 2;
                    mma_bf16(acc[mf][nf], ah[mf], bh[ng][hb], bh[ng][hb + 1]);
                    mma_bf16(acc[mf][nf], ah[mf], bl[ng][hb], bl[ng][hb + 1]);
                    mma_bf16(acc[mf][nf], al[mf], bh[ng][hb], bh[ng][hb + 1]);
                }
            }
        }
        __syncthreads();
    }

    // epilogue: fragment layout m16n8: lane g=lane>>2 row, ti=lane&3 col pair
    const int g  = lane >> 2;
    const int ti = lane & 3;
#pragma unroll
    for (int mf = 0; mf < 2; mf++) {
        const int row0 = bm + wm * 32 + mf * 16 + g;
#pragma unroll
        for (int nf = 0; nf < 4; nf++) {
            const int col = bn + wn * 32 + nf * 8 + ti * 2;
            const float b0 = __ldg(bias + col);
            const float b1 = __ldg(bias + col + 1);
            float2 o0, o1;
            o0.x = acc[mf][nf][0] + b0;
            o0.y = acc[mf][nf][1] + b1;
            o1.x = acc[mf][nf][2] + b0;
            o1.y = acc[mf][nf][3] + b1;
            *(float2*)(C + (size_t)row0 * N + col) = o0;
            *(float2*)(C + (size_t)(row0 + 8) * N + col) = o1;
        }
    }
}

// ---------------------------------------------------------------------------
// Flash-style attention (unchanged — known-correct fp32 SIMT)
// ---------------------------------------------------------------------------
__global__ __launch_bounds__(256) void attn_kernel(
    const float* __restrict__ Q, const float* __restrict__ K,
    const float* __restrict__ V, float* __restrict__ O)
{
    __shared__ float Qs[64][65];
    __shared__ float Ks[32][65];
    __shared__ float Vs[32][65];
    __shared__ float Ps[64][33];
    __shared__ float alpha_s[64];
    __shared__ float l_s[64];

    const int qt = blockIdx.x;
    const int bh = blockIdx.y;
    const int b  = bh >> 4;
    const int h  = bh & 15;

    const int tid = threadIdx.x;
    const int ty = tid >> 4;
    const int tx = tid & 15;

    const float* Qbase = Q + ((size_t)(b * SS + qt * 64) * DD) + h * HD;
    for (int i = tid; i < 64 * 16; i += 256) {
        int r = i >> 4;
        int c = (i & 15) * 4;
        float4 v = *(const float4*)(Qbase + (size_t)r * DD + c);
        Qs[r][c + 0] = v.x * 0.125f;
        Qs[r][c + 1] = v.y * 0.125f;
        Qs[r][c + 2] = v.z * 0.125f;
        Qs[r][c + 3] = v.w * 0.125f;
    }

    float m_r = -INFINITY;
    float l_r = 0.0f;

    float acc[4][4];
#pragma unroll
    for (int i = 0; i < 4; i++)
#pragma unroll
        for (int j = 0; j < 4; j++) acc[i][j] = 0.0f;

    for (int kt = 0; kt < SS / 32; kt++) {
        __syncthreads();

        const float* Kb2 = K + ((size_t)(b * SS + kt * 32) * DD) + h * HD;
        const float* Vb2 = V + ((size_t)(b * SS + kt * 32) * DD) + h * HD;
        for (int i = tid; i < 32 * 16; i += 256) {
            int r = i >> 4;
            int c = (i & 15) * 4;
            float4 kv = *(const float4*)(Kb2 + (size_t)r * DD + c);
            float4 vv = *(const float4*)(Vb2 + (size_t)r * DD + c);
            Ks[r][c + 0] = kv.x; Ks[r][c + 1] = kv.y;
            Ks[r][c + 2] = kv.z; Ks[r][c + 3] = kv.w;
            Vs[r][c + 0] = vv.x; Vs[r][c + 1] = vv.y;
            Vs[r][c + 2] = vv.z; Vs[r][c + 3] = vv.w;
        }
        __syncthreads();

        float s[4][2];
#pragma unroll
        for (int i = 0; i < 4; i++) { s[i][0] = 0.0f; s[i][1] = 0.0f; }
#pragma unroll 16
        for (int d = 0; d < 64; d++) {
            float k0 = Ks[tx * 2 + 0][d];
            float k1 = Ks[tx * 2 + 1][d];
#pragma unroll
            for (int i = 0; i < 4; i++) {
                float a = Qs[ty * 4 + i][d];
                s[i][0] = fmaf(a, k0, s[i][0]);
                s[i][1] = fmaf(a, k1, s[i][1]);
            }
        }
#pragma unroll
        for (int i = 0; i < 4; i++) {
            Ps[ty * 4 + i][tx * 2 + 0] = s[i][0];
            Ps[ty * 4 + i][tx * 2 + 1] = s[i][1];
        }
        __syncthreads();

        if (tid < 64) {
            float mx = m_r;
#pragma unroll
            for (int j = 0; j < 32; j++) mx = fmaxf(mx, Ps[tid][j]);
            float alpha = __expf(m_r - mx);
            float sum = 0.0f;
#pragma unroll
            for (int j = 0; j < 32; j++) {
                float p = __expf(Ps[tid][j] - mx);
                Ps[tid][j] = p;
                sum += p;
            }
            l_r = l_r * alpha + sum;
            m_r = mx;
            alpha_s[tid] = alpha;
        }
        __syncthreads();

        float al[4];
#pragma unroll
        for (int i = 0; i < 4; i++) al[i] = alpha_s[ty * 4 + i];
#pragma unroll
        for (int i = 0; i < 4; i++)
#pragma unroll
            for (int j = 0; j < 4; j++) acc[i][j] *= al[i];

#pragma unroll 8
        for (int j = 0; j < 32; j++) {
            float v0 = Vs[j][tx * 4 + 0];
            float v1 = Vs[j][tx * 4 + 1];
            float v2 = Vs[j][tx * 4 + 2];
            float v3 = Vs[j][tx * 4 + 3];
#pragma unroll
            for (int i = 0; i < 4; i++) {
                float p = Ps[ty * 4 + i][j];
                acc[i][0] = fmaf(p, v0, acc[i][0]);
                acc[i][1] = fmaf(p, v1, acc[i][1]);
                acc[i][2] = fmaf(p, v2, acc[i][2]);
                acc[i][3] = fmaf(p, v3, acc[i][3]);
            }
        }
    }

    if (tid < 64) l_s[tid] = l_r;
    __syncthreads();

    float inv[4];
#pragma unroll
    for (int i = 0; i < 4; i++) inv[i] = 1.0f / l_s[ty * 4 + i];

    float* Ob = O + ((size_t)(b * SS + qt * 64) * DD) + h * HD;
#pragma unroll
    for (int i = 0; i < 4; i++) {
        float4 o;
        o.x = acc[i][0] * inv[i];
        o.y = acc[i][1] * inv[i];
        o.z = acc[i][2] * inv[i];
        o.w = acc[i][3] * inv[i];
        *(float4*)(Ob + (size_t)(ty * 4 + i) * DD + tx * 4) = o;
    }
}

// ---------------------------------------------------------------------------
extern "C" void kernel_launch(void* const* d_in, const int* in_sizes, int n_in,
                              void* d_out, int out_size)
{
    const float* x  = (const float*)d_in[0];
    const float* Wq = (const float*)d_in[1];
    const float* bq = (const float*)d_in[2];
    const float* Wk = (const float*)d_in[3];
    const float* bk = (const float*)d_in[4];
    const float* Wv = (const float*)d_in[5];
    const float* bv = (const float*)d_in[6];
    const float* Wo = (const float*)d_in[7];
    const float* bo = (const float*)d_in[8];
    float* out = (float*)d_out;

    float *qp, *kp, *vp, *cp;
    cudaGetSymbolAddress((void**)&qp, g_Q);
    cudaGetSymbolAddress((void**)&kp, g_K);
    cudaGetSymbolAddress((void**)&vp, g_V);
    cudaGetSymbolAddress((void**)&cp, g_C);

    const int M = BB * SS;  // 8192
    dim3 gemm_grid(DD / GM_BN, M / GM_BM);  // (16, 64)

    gemm_mma<<<gemm_grid, 256>>>(x, Wq, bq, qp, M, DD, DD);
    gemm_mma<<<gemm_grid, 256>>>(x, Wk, bk, kp, M, DD, DD);
    gemm_mma<<<gemm_grid, 256>>>(x, Wv, bv, vp, M, DD, DD);

    dim3 attn_grid(SS / 64, BB * HH);   // (32, 64)
    attn_kernel<<<attn_grid, 256>>>(qp, kp, vp, cp);

    gemm_mma<<<gemm_grid, 256>>>(cp, Wo, bo, out, M, DD, DD);
}

// round 14
// speedup vs baseline: 4.1561x; 2.9370x over previous
#include <cuda_runtime.h>
#include <cuda_fp16.h>
#include <cuda_bf16.h>
#include <math.h>
#include <stdint.h>

#define BB 4
#define SS 2048
#define DD 1024
#define HH 16
#define HD 64

// Scratch (device globals: the sanctioned no-alloc workaround)
__device__ __half g_Qh[BB * SS * DD];
__device__ __half g_Kh[BB * SS * DD];
__device__ __half g_Vh[BB * SS * DD];
__device__ float  g_C [BB * SS * DD];

// ===========================================================================
// Helpers: ldmatrix + mma.sync (base-PTX, legal on target sm_103)
// ===========================================================================
__device__ __forceinline__ uint32_t smem_u32(const void* p) {
    uint32_t a;
    asm("{ .reg .u64 t; cvta.to.shared.u64 t, %1; cvt.u32.u64 %0, t; }"
        : "=r"(a) : "l"(p));
    return a;
}

__device__ __forceinline__ uint32_t h2_as_u32(__half2 h) {
    union { __half2 h2; uint32_t u; } c;
    c.h2 = h;
    return c.u;
}

#define LDSM4(r, addr) \
    asm volatile("ldmatrix.sync.aligned.m8n8.x4.shared.b16 {%0,%1,%2,%3}, [%4];" \
                 : "=r"((r)[0]), "=r"((r)[1]), "=r"((r)[2]), "=r"((r)[3]) \
                 : "r"(addr))

#define LDSM4T(r, addr) \
    asm volatile("ldmatrix.sync.aligned.m8n8.x4.trans.shared.b16 {%0,%1,%2,%3}, [%4];" \
                 : "=r"((r)[0]), "=r"((r)[1]), "=r"((r)[2]), "=r"((r)[3]) \
                 : "r"(addr))

__device__ __forceinline__ void mma_bf16(float* c, const uint32_t* a,
                                         uint32_t b0, uint32_t b1) {
    asm volatile(
        "mma.sync.aligned.m16n8k16.row.col.f32.bf16.bf16.f32 "
        "{%0,%1,%2,%3}, {%4,%5,%6,%7}, {%8,%9}, {%0,%1,%2,%3};"
        : "+f"(c[0]), "+f"(c[1]), "+f"(c[2]), "+f"(c[3])
        : "r"(a[0]), "r"(a[1]), "r"(a[2]), "r"(a[3]), "r"(b0), "r"(b1));
}

__device__ __forceinline__ void mma_f16(float* c, const uint32_t* a,
                                        uint32_t b0, uint32_t b1) {
    asm volatile(
        "mma.sync.aligned.m16n8k16.row.col.f32.f16.f16.f32 "
        "{%0,%1,%2,%3}, {%4,%5,%6,%7}, {%8,%9}, {%0,%1,%2,%3};"
        : "+f"(c[0]), "+f"(c[1]), "+f"(c[2]), "+f"(c[3])
        : "r"(a[0]), "r"(a[1]), "r"(a[2]), "r"(a[3]), "r"(b0), "r"(b1));
}

// fp32x4 -> packed bf16x4 hi and residual lo
__device__ __forceinline__ void split4(float4 v, unsigned long long& hi,
                                       unsigned long long& lo) {
    union { __nv_bfloat16 b[4]; unsigned long long u; } ph, pl;
    ph.b[0] = __float2bfloat16_rn(v.x);
    ph.b[1] = __float2bfloat16_rn(v.y);
    ph.b[2] = __float2bfloat16_rn(v.z);
    ph.b[3] = __float2bfloat16_rn(v.w);
    pl.b[0] = __float2bfloat16_rn(v.x - __bfloat162float(ph.b[0]));
    pl.b[1] = __float2bfloat16_rn(v.y - __bfloat162float(ph.b[1]));
    pl.b[2] = __float2bfloat16_rn(v.z - __bfloat162float(ph.b[2]));
    pl.b[3] = __float2bfloat16_rn(v.w - __bfloat162float(ph.b[3]));
    hi = ph.u;
    lo = pl.u;
}

__device__ __forceinline__ void store2(float* p, float a, float b) {
    float2 v; v.x = a; v.y = b;
    *(float2*)p = v;
}
__device__ __forceinline__ void store2(__half* p, float a, float b) {
    *(__half2*)p = __floats2half2_rn(a, b);
}

// ===========================================================================
// HMMA GEMM (bf16x3 split): C[M,N] = (A[M,K] * W[N,K]^T + bias) * oscale
// CTA tile 128x64, K-chunk 32, 256 threads (8 warps, warp tile 32x32).
// Smem rows padded to 40 bf16 (80B): 16B-aligned + conflict-free for ldmatrix.
// ===========================================================================
#define GM_BM 128
#define GM_BN 64
#define GM_BK 32
#define GM_PITCH 40

template <typename OutT>
__global__ __launch_bounds__(256) void gemm_mma(
    const float* __restrict__ A, const float* __restrict__ W,
    const float* __restrict__ bias, OutT* __restrict__ C,
    int M, int N, int K, float oscale)
{
    __shared__ __nv_bfloat16 Ah[GM_BM][GM_PITCH];
    __shared__ __nv_bfloat16 Al[GM_BM][GM_PITCH];
    __shared__ __nv_bfloat16 Bh[GM_BN][GM_PITCH];
    __shared__ __nv_bfloat16 Bl[GM_BN][GM_PITCH];

    const int tid  = threadIdx.x;
    const int wid  = tid >> 5;
    const int lane = tid & 31;
    const int wm   = wid >> 1;   // 0..3 -> M offset wm*32
    const int wn   = wid & 1;    // 0..1 -> N offset wn*32

    const int bm = blockIdx.y * GM_BM;
    const int bn = blockIdx.x * GM_BN;

    const int ar = tid >> 3;          // 0..31
    const int ac = (tid & 7) * 4;     // 0,4,...,28

    const int la_row = (lane & 7) + ((lane >> 3) & 1) * 8;
    const int la_kc  = (lane >> 4) * 8;
    const int lb_row = ((lane >> 4) & 1) * 8 + (lane & 7);
    const int lb_kc  = ((lane >> 3) & 1) * 8;

    float acc[2][4][4];
#pragma unroll
    for (int mf = 0; mf < 2; mf++)
#pragma unroll
        for (int nf = 0; nf < 4; nf++)
#pragma unroll
            for (int i = 0; i < 4; i++) acc[mf][nf][i] = 0.0f;

    float4 a_st[4];
    float4 b_st[2];

#pragma unroll
    for (int it = 0; it < 4; it++)
        a_st[it] = *(const float4*)(A + (size_t)(bm + ar + it * 32) * K + ac);
#pragma unroll
    for (int it = 0; it < 2; it++)
        b_st[it] = *(const float4*)(W + (size_t)(bn + ar + it * 32) * K + ac);

    const int nchunks = K / GM_BK;
    for (int ch = 0; ch < nchunks; ch++) {
#pragma unroll
        for (int it = 0; it < 4; it++) {
            unsigned long long hi, lo;
            split4(a_st[it], hi, lo);
            *(unsigned long long*)&Ah[ar + it * 32][ac] = hi;
            *(unsigned long long*)&Al[ar + it * 32][ac] = lo;
        }
#pragma unroll
        for (int it = 0; it < 2; it++) {
            unsigned long long hi, lo;
            split4(b_st[it], hi, lo);
            *(unsigned long long*)&Bh[ar + it * 32][ac] = hi;
            *(unsigned long long*)&Bl[ar + it * 32][ac] = lo;
        }
        __syncthreads();

        if (ch + 1 < nchunks) {
            const int k0 = (ch + 1) * GM_BK;
#pragma unroll
            for (int it = 0; it < 4; it++)
                a_st[it] = *(const float4*)(A + (size_t)(bm + ar + it * 32) * K + k0 + ac);
#pragma unroll
            for (int it = 0; it < 2; it++)
                b_st[it] = *(const float4*)(W + (size_t)(bn + ar + it * 32) * K + k0 + ac);
        }

#pragma unroll
        for (int ks = 0; ks < 2; ks++) {
            uint32_t ah[2][4], al[2][4];
            uint32_t bh[2][4], bl[2][4];
#pragma unroll
            for (int mf = 0; mf < 2; mf++) {
                const int r = wm * 32 + mf * 16 + la_row;
                const int c = ks * 16 + la_kc;
                LDSM4(ah[mf], smem_u32(&Ah[r][c]));
                LDSM4(al[mf], smem_u32(&Al[r][c]));
            }
#pragma unroll
            for (int ng = 0; ng < 2; ng++) {
                const int r = wn * 32 + ng * 16 + lb_row;
                const int c = ks * 16 + lb_kc;
                LDSM4(bh[ng], smem_u32(&Bh[r][c]));
                LDSM4(bl[ng], smem_u32(&Bl[r][c]));
            }
#pragma unroll
            for (int mf = 0; mf < 2; mf++) {
#pragma unroll
                for (int nf = 0; nf < 4; nf++) {
                    const int ng = nf >> 1;
                    const int hb = (nf & 1) * 2;
                    mma_bf16(acc[mf][nf], ah[mf], bh[ng][hb], bh[ng][hb + 1]);
                    mma_bf16(acc[mf][nf], ah[mf], bl[ng][hb], bl[ng][hb + 1]);
                    mma_bf16(acc[mf][nf], al[mf], bh[ng][hb], bh[ng][hb + 1]);
                }
            }
        }
        __syncthreads();
    }

    const int g  = lane >> 2;
    const int ti = lane & 3;
#pragma unroll
    for (int mf = 0; mf < 2; mf++) {
        const int row0 = bm + wm * 32 + mf * 16 + g;
#pragma unroll
        for (int nf = 0; nf < 4; nf++) {
            const int col = bn + wn * 32 + nf * 8 + ti * 2;
            const float b0 = __ldg(bias + col);
            const float b1 = __ldg(bias + col + 1);
            store2(C + (size_t)row0 * N + col,
                   (acc[mf][nf][0] + b0) * oscale, (acc[mf][nf][1] + b1) * oscale);
            store2(C + (size_t)(row0 + 8) * N + col,
                   (acc[mf][nf][2] + b0) * oscale, (acc[mf][nf][3] + b1) * oscale);
        }
    }
}

// ===========================================================================
// HMMA flash attention (fp16 inputs, fp32 accumulate).
// Grid (S/128, B*H), 256 threads (8 warps), warp owns 16 q-rows.
// KV tiles of 64 keys. Q fragments register-resident for the whole loop.
// ===========================================================================
#define AT_PITCH 72   // halves; 144B row pitch -> conflict-free ldmatrix

__global__ __launch_bounds__(256, 2) void attn_mma(
    const __half* __restrict__ Q, const __half* __restrict__ K,
    const __half* __restrict__ V, float* __restrict__ O)
{
    __shared__ __half Qs[128][AT_PITCH];
    __shared__ __half Ks[64][AT_PITCH];
    __shared__ __half Vs[64][AT_PITCH];

    const int qt  = blockIdx.x;
    const int bh  = blockIdx.y;
    const int b   = bh >> 4;
    const int h   = bh & 15;
    const int tid = threadIdx.x;
    const int wid = tid >> 5;
    const int lane = tid & 31;
    const int g  = lane >> 2;
    const int ti = lane & 3;

    // load Q tile (fp16, pre-scaled by 1/8 in projection epilogue)
    const __half* Qg = Q + (size_t)(b * SS + qt * 128) * DD + h * HD;
    for (int i = tid; i < 128 * 8; i += 256) {
        int r = i >> 3, c = (i & 7) * 8;
        *(uint4*)&Qs[r][c] = *(const uint4*)(Qg + (size_t)r * DD + c);
    }
    __syncthreads();

    const int la_row = (lane & 7) + ((lane >> 3) & 1) * 8;
    const int la_kc  = (lane >> 4) * 8;
    const int lb_row = ((lane >> 4) & 1) * 8 + (lane & 7);
    const int lb_kc  = ((lane >> 3) & 1) * 8;
    const int lv_row = ((lane >> 3) & 1) * 8 + (lane & 7);
    const int lv_dc  = ((lane >> 4) & 1) * 8;

    uint32_t qf[4][4];
#pragma unroll
    for (int ks = 0; ks < 4; ks++)
        LDSM4(qf[ks], smem_u32(&Qs[wid * 16 + la_row][ks * 16 + la_kc]));

    float m0 = -INFINITY, m1 = -INFINITY;
    float l0 = 0.0f, l1 = 0.0f;
    float o[8][4];
#pragma unroll
    for (int j = 0; j < 8; j++)
#pragma unroll
        for (int i = 0; i < 4; i++) o[j][i] = 0.0f;

    for (int kt = 0; kt < SS / 64; kt++) {
        __syncthreads();  // guard Ks/Vs reuse
        const __half* Kg = K + (size_t)(b * SS + kt * 64) * DD + h * HD;
        const __half* Vg = V + (size_t)(b * SS + kt * 64) * DD + h * HD;
        for (int i = tid; i < 64 * 8; i += 256) {
            int r = i >> 3, c = (i & 7) * 8;
            *(uint4*)&Ks[r][c] = *(const uint4*)(Kg + (size_t)r * DD + c);
            *(uint4*)&Vs[r][c] = *(const uint4*)(Vg + (size_t)r * DD + c);
        }
        __syncthreads();

        // S = Q K^T  (fp32 fragments; 8 n-tiles of 8 keys)
        float s[8][4];
#pragma unroll
        for (int j = 0; j < 8; j++)
#pragma unroll
            for (int i = 0; i < 4; i++) s[j][i] = 0.0f;

#pragma unroll
        for (int ks = 0; ks < 4; ks++) {
            uint32_t kf[4][4];
#pragma unroll
            for (int kg = 0; kg < 4; kg++)
                LDSM4(kf[kg], smem_u32(&Ks[kg * 16 + lb_row][ks * 16 + lb_kc]));
#pragma unroll
            for (int kg = 0; kg < 4; kg++) {
                mma_f16(s[kg * 2],     qf[ks], kf[kg][0], kf[kg][1]);
                mma_f16(s[kg * 2 + 1], qf[ks], kf[kg][2], kf[kg][3]);
            }
        }

        // online softmax (rows g and g+8 per thread; quad lanes share a row)
        float mx0 = m0, mx1 = m1;
#pragma unroll
        for (int j = 0; j < 8; j++) {
            mx0 = fmaxf(mx0, fmaxf(s[j][0], s[j][1]));
            mx1 = fmaxf(mx1, fmaxf(s[j][2], s[j][3]));
        }
        mx0 = fmaxf(mx0, __shfl_xor_sync(0xFFFFFFFF, mx0, 1));
        mx0 = fmaxf(mx0, __shfl_xor_sync(0xFFFFFFFF, mx0, 2));
        mx1 = fmaxf(mx1, __shfl_xor_sync(0xFFFFFFFF, mx1, 1));
        mx1 = fmaxf(mx1, __shfl_xor_sync(0xFFFFFFFF, mx1, 2));

        const float alpha0 = __expf(m0 - mx0);
        const float alpha1 = __expf(m1 - mx1);
        m0 = mx0; m1 = mx1;

        float rs0 = 0.0f, rs1 = 0.0f;
        uint32_t ph[8][2];
#pragma unroll
        for (int j = 0; j < 8; j++) {
            float p0 = __expf(s[j][0] - m0);
            float p1 = __expf(s[j][1] - m0);
            float p2 = __expf(s[j][2] - m1);
            float p3 = __expf(s[j][3] - m1);
            rs0 += p0 + p1;
            rs1 += p2 + p3;
            ph[j][0] = h2_as_u32(__floats2half2_rn(p0, p1));
            ph[j][1] = h2_as_u32(__floats2half2_rn(p2, p3));
        }
        rs0 += __shfl_xor_sync(0xFFFFFFFF, rs0, 1);
        rs0 += __shfl_xor_sync(0xFFFFFFFF, rs0, 2);
        rs1 += __shfl_xor_sync(0xFFFFFFFF, rs1, 1);
        rs1 += __shfl_xor_sync(0xFFFFFFFF, rs1, 2);
        l0 = l0 * alpha0 + rs0;
        l1 = l1 * alpha1 + rs1;

#pragma unroll
        for (int j = 0; j < 8; j++) {
            o[j][0] *= alpha0; o[j][1] *= alpha0;
            o[j][2] *= alpha1; o[j][3] *= alpha1;
        }

        // O += P V   (4 k16-steps over keys; ldmatrix.trans on row-major V)
#pragma unroll
        for (int t = 0; t < 4; t++) {
            uint32_t a[4] = { ph[2 * t][0], ph[2 * t][1],
                              ph[2 * t + 1][0], ph[2 * t + 1][1] };
#pragma unroll
            for (int dg = 0; dg < 4; dg++) {
                uint32_t vf[4];
                LDSM4T(vf, smem_u32(&Vs[t * 16 + lv_row][dg * 16 + lv_dc]));
                mma_f16(o[dg * 2],     a, vf[0], vf[1]);
                mma_f16(o[dg * 2 + 1], a, vf[2], vf[3]);
            }
        }
    }

    const float inv0 = 1.0f / l0;
    const float inv1 = 1.0f / l1;
    float* Og = O + (size_t)(b * SS + qt * 128 + wid * 16) * DD + h * HD;
#pragma unroll
    for (int j = 0; j < 8; j++) {
        float2 v0, v1;
        v0.x = o[j][0] * inv0; v0.y = o[j][1] * inv0;
        v1.x = o[j][2] * inv1; v1.y = o[j][3] * inv1;
        *(float2*)(Og + (size_t)g * DD + j * 8 + ti * 2) = v0;
        *(float2*)(Og + (size_t)(g + 8) * DD + j * 8 + ti * 2) = v1;
    }
}

// ---------------------------------------------------------------------------
extern "C" void kernel_launch(void* const* d_in, const int* in_sizes, int n_in,
                              void* d_out, int out_size)
{
    const float* x  = (const float*)d_in[0];
    const float* Wq = (const float*)d_in[1];
    const float* bq = (const float*)d_in[2];
    const float* Wk = (const float*)d_in[3];
    const float* bk = (const float*)d_in[4];
    const float* Wv = (const float*)d_in[5];
    const float* bv = (const float*)d_in[6];
    const float* Wo = (const float*)d_in[7];
    const float* bo = (const float*)d_in[8];
    float* out = (float*)d_out;

    __half *qh, *kh, *vh;
    float *cp;
    cudaGetSymbolAddress((void**)&qh, g_Qh);
    cudaGetSymbolAddress((void**)&kh, g_Kh);
    cudaGetSymbolAddress((void**)&vh, g_Vh);
    cudaGetSymbolAddress((void**)&cp, g_C);

    const int M = BB * SS;  // 8192
    dim3 gemm_grid(DD / GM_BN, M / GM_BM);  // (16, 64)

    gemm_mma<__half><<<gemm_grid, 256>>>(x, Wq, bq, qh, M, DD, DD, 0.125f);
    gemm_mma<__half><<<gemm_grid, 256>>>(x, Wk, bk, kh, M, DD, DD, 1.0f);
    gemm_mma<__half><<<gemm_grid, 256>>>(x, Wv, bv, vh, M, DD, DD, 1.0f);

    dim3 attn_grid(SS / 128, BB * HH);   // (16, 64)
    attn_mma<<<attn_grid, 256>>>(qh, kh, vh, cp);

    gemm_mma<float><<<gemm_grid, 256>>>(cp, Wo, bo, out, M, DD, DD, 1.0f);
}